// round 17
// baseline (speedup 1.0000x reference)
#include <cuda_runtime.h>
#include <cstdint>

#define NBLK    128
#define FEAT    32
#define THREADS 128
#define NBATCH  1024

#define NCHUNK   8            // k-chunks of 16 (one m16n8k16 step each)
#define CHUNK_K  16
#define AW_FLOATS 512         // 32 rows x 16 floats, XOR-swizzled, NO pad
#define NSTAGE   2
#define A_BYTES  (4 * NSTAGE * AW_FLOATS * 4)   // 16384
#define B_BYTES  (32 * 128 * 4)                 // 16384 (flat, XOR-swizzled)
#define SMEM_BYTES (A_BYTES + B_BYTES)          // 32768 -> 7 CTAs/SM: SINGLE WAVE

// m16n8k16 bf16 mma: D += A*B, fp32 accumulate.
__device__ __forceinline__ void mma_bf16(float* d, uint32_t a0, uint32_t a1,
                                         uint32_t a2, uint32_t a3,
                                         uint32_t b0, uint32_t b1) {
    asm("mma.sync.aligned.m16n8k16.row.col.f32.bf16.bf16.f32 "
        "{%0,%1,%2,%3}, {%4,%5,%6,%7}, {%8,%9}, {%0,%1,%2,%3};"
        : "+f"(d[0]), "+f"(d[1]), "+f"(d[2]), "+f"(d[3])
        : "r"(a0), "r"(a1), "r"(a2), "r"(a3), "r"(b0), "r"(b1));
}

// pack bf16x2: x -> low half, y -> high half
__device__ __forceinline__ uint32_t pack_bf16(float x, float y) {
    uint32_t d;
    asm("cvt.rn.bf16x2.f32 %0, %1, %2;" : "=r"(d) : "f"(y), "f"(x));
    return d;
}
// Split fp32 pair into bf16 hi pack + bf16 residual pack (residual exact in fp32).
__device__ __forceinline__ void split_pair(float x, float y, uint32_t& h, uint32_t& l) {
    h = pack_bf16(x, y);
    float hx = __uint_as_float(h << 16);
    float hy = __uint_as_float(h & 0xFFFF0000u);
    l = pack_bf16(x - hx, y - hy);
}

__device__ __forceinline__ uint32_t smem_u32adr(const void* p) {
    uint32_t a;
    asm("{ .reg .u64 t; cvta.to.shared.u64 t, %1; cvt.u32.u64 %0, t; }" : "=r"(a) : "l"(p));
    return a;
}
__device__ __forceinline__ void cp16(uint32_t dst, const void* src) {
    asm volatile("cp.async.cg.shared.global [%0], [%1], 16;" :: "r"(dst), "l"(src));
}
#define CP_COMMIT()  asm volatile("cp.async.commit_group;" ::: "memory")
#define CP_WAIT(n)   asm volatile("cp.async.wait_group %0;" :: "n"(n) : "memory")

// Per CTA: out[128,32] = W[idx[b]] @ x[b] via 3xBF16-split m16n8k16 mma.sync.
// SINGLE-WAVE configuration: 32KB smem -> 7 CTAs/SM x 148 SM = 1036 slots >=
// 1024 CTAs, so the whole grid is resident at once (no wave-quantization
// makespan doubling). A: warp-private 2-stage pad-free swizzled ring,
// in-flight ~2 groups (issue ck+2 right after chunk ck's A-frag consumption).
// B: flat [32 n][128 w] u32 with XOR swizzle w^(4*(n&7)) -> in-loop LDS.32
// conflict-free; hi packs at w in [0,64), lo packs at [64,128).
// Per-nt MMA emission keeps live regs under the 73-reg cap.
__global__ void __launch_bounds__(THREADS, 7) bmm_mma_kernel(
    const float* __restrict__ inp,
    const float* __restrict__ W,
    const int*   __restrict__ idx_raw,
    float* __restrict__ out)
{
    extern __shared__ char smem[];
    float*    As = (float*)smem;                 // per-warp: 2 stages x 512 floats
    uint32_t* Bs = (uint32_t*)(smem + A_BYTES);  // [32 n][128 w] swizzled

    const int blk = blockIdx.x;
    const int tid = threadIdx.x;
    const int wid = tid >> 5;
    const int lid = tid & 31;
    const int gid = lid >> 2;         // groupID 0..7
    const int tig = lid & 3;          // thread-in-group 0..3

    // ---- Inline index resolution: int64 (odd words all 0) vs int32 ----
    int odd = idx_raw[1] | idx_raw[3] | idx_raw[5] | idx_raw[7] | idx_raw[9];
    int g = odd ? idx_raw[blk] : idx_raw[2 * blk];
    g = (g < 0) ? 0 : ((g >= 1024) ? 1023 : g);

    // Warp-private A region and gmem row base (warp w owns rows [32w, 32w+32)).
    const float* Wg = W + (long long)g * (NBLK * NBLK) + (wid * 32) * NBLK;
    float* Aw = As + wid * (NSTAGE * AW_FLOATS);

    // One warp-chunk = 32 rows x 16 floats; 4 cp.async per lane, swizzled dst.
    #define ISSUE_CHUNK(ck, buf) do {                                            \
        const float* srcb = Wg + (ck) * CHUNK_K;                                 \
        float* dstb = Aw + (buf) * AW_FLOATS;                                    \
        _Pragma("unroll")                                                        \
        for (int it = 0; it < 4; ++it) {                                         \
            int c = lid + 32 * it;                                               \
            int row = c >> 2, slot = c & 3;                                      \
            cp16(smem_u32adr(dstb + row * 16 + ((slot ^ (row & 3)) << 2)),       \
                 srcb + row * NBLK + slot * 4);                                  \
        }                                                                        \
        CP_COMMIT();                                                             \
    } while (0)

    ISSUE_CHUNK(0, 0);
    ISSUE_CHUNK(1, 1);

    // ---- Stage B pre-split: hi at Bs[n*128 + (p^(4*(n&7)))], lo at +64 ----
    {
        const float* xb = inp + (long long)blk * NBLK * FEAT;
        #pragma unroll
        for (int it = 0; it < 4; ++it) {
            int q  = tid + THREADS * it;       // 0..511
            int p  = q >> 3;                   // pair: k = 2p, 2p+1  (0..63)
            int nb = (q & 7) * 4;
            float4 v0 = *(const float4*)(xb + (2 * p)     * FEAT + nb);
            float4 v1 = *(const float4*)(xb + (2 * p + 1) * FEAT + nb);
            const float e0[4] = {v0.x, v0.y, v0.z, v0.w};
            const float e1[4] = {v1.x, v1.y, v1.z, v1.w};
            #pragma unroll
            for (int j = 0; j < 4; ++j) {
                uint32_t h, l;
                split_pair(e0[j], e1[j], h, l);
                int n  = nb + j;
                int ws = p ^ ((n & 7) << 2);
                Bs[n * 128 + ws]      = h;
                Bs[n * 128 + 64 + ws] = l;
            }
        }
    }
    __syncthreads();   // the ONLY CTA-wide barrier: B visible to all warps

    float d[2][4][4];
    #pragma unroll
    for (int mt = 0; mt < 2; ++mt)
        #pragma unroll
        for (int nt = 0; nt < 4; ++nt)
            #pragma unroll
            for (int e = 0; e < 4; ++e) d[mt][nt][e] = 0.0f;

    // Per-thread constant swizzled A column offsets:
    const int acol_lo = (2 * tig) ^ ((gid & 3) << 2);   // cols 2tig,2tig+1
    const int acol_hi = acol_lo ^ 8;                    // cols 2tig+8,2tig+9
    const int bxor    = gid << 2;                       // B swizzle constant
    const uint32_t* b_n0 = Bs + gid * 128;              // n = nt*8+gid -> +nt*1024

    #pragma unroll
    for (int ck = 0; ck < NCHUNK; ++ck) {
        if (ck < NCHUNK - 1) { CP_WAIT(1); } else { CP_WAIT(0); }
        __syncwarp();     // cross-lane smem visibility within the warp

        // ---- A fragments: swizzled float2 LDS, bf16 split ----
        const float* a_stage = Aw + (ck & 1) * AW_FLOATS + gid * 16;
        uint32_t ah[2][4], al[2][4];
        #pragma unroll
        for (int mt = 0; mt < 2; ++mt) {
            const float* p = a_stage + mt * (16 * 16);          // +16 rows
            float2 v0 = *(const float2*)(p + acol_lo);          // (r0,   k0,k0+1)
            float2 v1 = *(const float2*)(p + 128 + acol_lo);    // (r0+8, k0,k0+1)
            float2 v2 = *(const float2*)(p + acol_hi);          // (r0,   k0+8,+9)
            float2 v3 = *(const float2*)(p + 128 + acol_hi);    // (r0+8, k0+8,+9)
            split_pair(v0.x, v0.y, ah[mt][0], al[mt][0]);
            split_pair(v1.x, v1.y, ah[mt][1], al[mt][1]);
            split_pair(v2.x, v2.y, ah[mt][2], al[mt][2]);
            split_pair(v3.x, v3.y, ah[mt][3], al[mt][3]);
        }

        // A frags consumed from smem (splits above depend on the LDS results),
        // so buffer ck&1 is safe to refill now. Keeps ~2 groups in flight.
        if (ck + 2 < NCHUNK) ISSUE_CHUNK(ck + 2, ck & 1);

        // ---- B per-nt: 4 LDS.32 (conflict-free) + 6 MMAs, low live regs ----
        const int w0 = ((ck * 8 + tig) ^ bxor);
        #pragma unroll
        for (int nt = 0; nt < 4; ++nt) {
            const uint32_t* p = b_n0 + nt * 1024;
            uint32_t bh0 = p[w0];
            uint32_t bh1 = p[w0 ^ 4];
            uint32_t bl0 = p[w0 + 64];
            uint32_t bl1 = p[(w0 ^ 4) + 64];
            #pragma unroll
            for (int mt = 0; mt < 2; ++mt) {
                mma_bf16(d[mt][nt], ah[mt][0], ah[mt][1], ah[mt][2], ah[mt][3], bh0, bh1);
                mma_bf16(d[mt][nt], al[mt][0], al[mt][1], al[mt][2], al[mt][3], bh0, bh1);
                mma_bf16(d[mt][nt], ah[mt][0], ah[mt][1], ah[mt][2], ah[mt][3], bl0, bl1);
            }
        }
    }

    // ---- Epilogue: write D fragments straight to gmem (float2 per pair) ----
    float* ob = out + (long long)blk * NBLK * FEAT;
    #pragma unroll
    for (int mt = 0; mt < 2; ++mt) {
        const int r0 = wid * 32 + mt * 16 + gid;
        #pragma unroll
        for (int nt = 0; nt < 4; ++nt) {
            const int c = nt * 8 + tig * 2;
            *(float2*)(ob + r0 * FEAT + c)       = make_float2(d[mt][nt][0], d[mt][nt][1]);
            *(float2*)(ob + (r0 + 8) * FEAT + c) = make_float2(d[mt][nt][2], d[mt][nt][3]);
        }
    }
}

extern "C" void kernel_launch(void* const* d_in, const int* in_sizes, int n_in,
                              void* d_out, int out_size) {
    // Select pointers by element count (robust to metadata ordering).
    const float* inp = nullptr;
    const float* W   = nullptr;
    const void*  idx = nullptr;
    for (int i = 0; i < n_in; ++i) {
        if      (in_sizes[i] == 4194304)  inp = (const float*)d_in[i];
        else if (in_sizes[i] == 16777216) W   = (const float*)d_in[i];
        else if (in_sizes[i] == 1024)     idx = d_in[i];
    }

    cudaFuncSetAttribute(bmm_mma_kernel, cudaFuncAttributeMaxDynamicSharedMemorySize,
                         SMEM_BYTES);
    bmm_mma_kernel<<<NBATCH, THREADS, SMEM_BYTES>>>(inp, W, (const int*)idx,
                                                    (float*)d_out);
}